// round 2
// baseline (speedup 1.0000x reference)
#include <cuda_runtime.h>
#include <cstdint>

// Problem shapes (fixed by the dataset)
#define ROWS      16384
#define PRED_COLS 100
#define TRUE_COLS 50
#define KK        50
#define TPB       128
#define NBLOCKS   (ROWS / TPB)   // 128

// Per-block partial sums (scratch; allocation-free per harness rules)
__device__ float g_partials[NBLOCKS];

__global__ __launch_bounds__(TPB) void mapk_kernel(
    const int* __restrict__ y_pred,
    const int* __restrict__ y_true,
    const float* __restrict__ multiplier)
{
    // [word][tid] layout: bank = tid % 32 -> each lane owns a private bank,
    // conflict-free for arbitrary dynamic word indices.
    __shared__ unsigned int masks[64 * TPB];   // words 0..31: true bitmap, 32..63: seen bitmap
    __shared__ float smult[KK];
    __shared__ float warp_sums[TPB / 32];

    const int tid = threadIdx.x;
    if (tid < KK) smult[tid] = multiplier[tid];

    #pragma unroll
    for (int w = 0; w < 64; ++w)
        masks[w * TPB + tid] = 0u;
    __syncthreads();   // smult visibility (masks are per-thread-private banks)

    const int row = blockIdx.x * TPB + tid;

    // --- build true bitmap (values in [0,1000) < 1024) ---
    const int* tr = y_true + (long long)row * TRUE_COLS;
    #pragma unroll
    for (int j = 0; j < TRUE_COLS; ++j) {
        unsigned int v = (unsigned int)tr[j];
        masks[(v >> 5) * TPB + tid] |= (1u << (v & 31u));
    }

    // --- scan preds: hit = in-true && not-seen-before ---
    const int* pr = y_pred + (long long)row * PRED_COLS;
    float score = 0.0f;
    int cnt = 0;
    #pragma unroll
    for (int i = 0; i < KK; ++i) {
        unsigned int v   = (unsigned int)pr[i];
        unsigned int bit = 1u << (v & 31u);
        unsigned int w   = v >> 5;
        unsigned int tm  = masks[w * TPB + tid];
        unsigned int sm  = masks[(32u + w) * TPB + tid];
        bool hit = (tm & bit) && !(sm & bit);
        masks[(32u + w) * TPB + tid] = sm | bit;
        if (hit) {
            ++cnt;
            score += (float)cnt * smult[i];
        }
    }
    score *= (1.0f / (float)TRUE_COLS);   // denom = min(50, 50) = 50

    // --- block reduction (deterministic) ---
    #pragma unroll
    for (int off = 16; off > 0; off >>= 1)
        score += __shfl_down_sync(0xFFFFFFFFu, score, off);
    if ((tid & 31) == 0) warp_sums[tid >> 5] = score;
    __syncthreads();
    if (tid == 0) {
        float s = 0.0f;
        #pragma unroll
        for (int w = 0; w < TPB / 32; ++w) s += warp_sums[w];
        g_partials[blockIdx.x] = s;
    }
}

__global__ __launch_bounds__(NBLOCKS) void finalize_kernel(float* __restrict__ out)
{
    __shared__ float warp_sums[NBLOCKS / 32];
    int tid = threadIdx.x;
    float v = g_partials[tid];
    #pragma unroll
    for (int off = 16; off > 0; off >>= 1)
        v += __shfl_down_sync(0xFFFFFFFFu, v, off);
    if ((tid & 31) == 0) warp_sums[tid >> 5] = v;
    __syncthreads();
    if (tid == 0) {
        float s = 0.0f;
        #pragma unroll
        for (int w = 0; w < NBLOCKS / 32; ++w) s += warp_sums[w];
        out[0] = s * (1.0f / (float)ROWS);
    }
}

extern "C" void kernel_launch(void* const* d_in, const int* in_sizes, int n_in,
                              void* d_out, int out_size)
{
    // Assign inputs by element count (robust to metadata ordering):
    //   16384*100 = 1638400 -> y_pred
    //   16384*50  =  819200 -> y_true
    //   50                  -> multiplier
    const int*   y_pred = nullptr;
    const int*   y_true = nullptr;
    const float* mult   = nullptr;
    for (int i = 0; i < n_in; ++i) {
        if      (in_sizes[i] == ROWS * PRED_COLS) y_pred = (const int*)d_in[i];
        else if (in_sizes[i] == ROWS * TRUE_COLS) y_true = (const int*)d_in[i];
        else if (in_sizes[i] == KK)               mult   = (const float*)d_in[i];
    }
    float* out = (float*)d_out;

    mapk_kernel<<<NBLOCKS, TPB>>>(y_pred, y_true, mult);
    finalize_kernel<<<1, NBLOCKS>>>(out);
}

// round 3
// speedup vs baseline: 1.2759x; 1.2759x over previous
#include <cuda_runtime.h>
#include <cstdint>

// Problem shapes (fixed by the dataset)
#define ROWS      16384
#define PRED_COLS 100
#define TRUE_COLS 50
#define KK        50
#define TPB       64
#define NBLOCKS   (ROWS / TPB)   // 256

// Scratch (allocation-free per harness rules)
__device__ float        g_partials[NBLOCKS];
__device__ unsigned int g_count = 0;   // reset by last block each run -> replay-safe

__global__ __launch_bounds__(TPB) void mapk_fused_kernel(
    const int*   __restrict__ y_pred,
    const int*   __restrict__ y_true,
    const float* __restrict__ multiplier,
    float*       __restrict__ out)
{
    // Single bitmap: bit set = value is in y_true AND not yet consumed.
    // [word][tid] layout: bank = tid % 32 -> each lane owns a private bank,
    // conflict-free for arbitrary dynamic word indices.
    __shared__ unsigned int masks[32 * TPB];
    __shared__ float smult[KK];
    __shared__ float red[TPB / 32];
    __shared__ bool  is_last;

    const int tid = threadIdx.x;
    if (tid < KK) smult[tid] = multiplier[tid];

    #pragma unroll
    for (int w = 0; w < 32; ++w)
        masks[w * TPB + tid] = 0u;
    __syncthreads();

    const int row = blockIdx.x * TPB + tid;

    // --- build true bitmap (values in [0,1000) < 1024), int2-vectorized ---
    const int2* tr2 = (const int2*)(y_true + (long long)row * TRUE_COLS);
    #pragma unroll
    for (int j = 0; j < TRUE_COLS / 2; ++j) {
        int2 t = tr2[j];
        unsigned int a = (unsigned int)t.x;
        unsigned int b = (unsigned int)t.y;
        masks[(a >> 5) * TPB + tid] |= (1u << (a & 31u));
        masks[(b >> 5) * TPB + tid] |= (1u << (b & 31u));
    }

    // --- scan preds: hit = bit set; consume (clear) on hit.
    //     Clearing is equivalent to match & ~dup (dups find bit cleared;
    //     dups of non-matches never match). ---
    const int2* pr2 = (const int2*)(y_pred + (long long)row * PRED_COLS);
    float score = 0.0f;
    float cnt   = 0.0f;
    #pragma unroll
    for (int j = 0; j < KK / 2; ++j) {
        int2 p = pr2[j];
        {
            unsigned int v   = (unsigned int)p.x;
            unsigned int bit = 1u << (v & 31u);
            unsigned int idx = (v >> 5) * TPB + tid;
            unsigned int tm  = masks[idx];
            if (tm & bit) {
                masks[idx] = tm & ~bit;
                cnt += 1.0f;
                score += cnt * smult[2 * j];
            }
        }
        {
            unsigned int v   = (unsigned int)p.y;
            unsigned int bit = 1u << (v & 31u);
            unsigned int idx = (v >> 5) * TPB + tid;
            unsigned int tm  = masks[idx];
            if (tm & bit) {
                masks[idx] = tm & ~bit;
                cnt += 1.0f;
                score += cnt * smult[2 * j + 1];
            }
        }
    }
    // per-row /50 and mean /16384 folded into one final scale

    // --- block reduction (deterministic) ---
    #pragma unroll
    for (int off = 16; off > 0; off >>= 1)
        score += __shfl_down_sync(0xFFFFFFFFu, score, off);
    if ((tid & 31) == 0) red[tid >> 5] = score;
    __syncthreads();
    if (tid == 0) {
        float s = 0.0f;
        #pragma unroll
        for (int w = 0; w < TPB / 32; ++w) s += red[w];
        g_partials[blockIdx.x] = s;
        __threadfence();
        unsigned int prev = atomicAdd(&g_count, 1u);
        is_last = (prev == NBLOCKS - 1);
    }
    __syncthreads();

    // --- last block: deterministic final reduction + counter reset ---
    if (is_last) {
        float v = 0.0f;
        #pragma unroll
        for (int k = 0; k < NBLOCKS / TPB; ++k)     // fixed order per thread
            v += g_partials[tid + k * TPB];
        #pragma unroll
        for (int off = 16; off > 0; off >>= 1)
            v += __shfl_down_sync(0xFFFFFFFFu, v, off);
        if ((tid & 31) == 0) red[tid >> 5] = v;
        __syncthreads();
        if (tid == 0) {
            float s = 0.0f;
            #pragma unroll
            for (int w = 0; w < TPB / 32; ++w) s += red[w];
            out[0] = s * (1.0f / ((float)TRUE_COLS * (float)ROWS));
            g_count = 0;   // reset for next graph replay
        }
    }
}

extern "C" void kernel_launch(void* const* d_in, const int* in_sizes, int n_in,
                              void* d_out, int out_size)
{
    // Assign inputs by element count (robust to metadata ordering):
    //   16384*100 = 1638400 -> y_pred
    //   16384*50  =  819200 -> y_true
    //   50                  -> multiplier
    const int*   y_pred = nullptr;
    const int*   y_true = nullptr;
    const float* mult   = nullptr;
    for (int i = 0; i < n_in; ++i) {
        if      (in_sizes[i] == ROWS * PRED_COLS) y_pred = (const int*)d_in[i];
        else if (in_sizes[i] == ROWS * TRUE_COLS) y_true = (const int*)d_in[i];
        else if (in_sizes[i] == KK)               mult   = (const float*)d_in[i];
    }
    float* out = (float*)d_out;

    mapk_fused_kernel<<<NBLOCKS, TPB>>>(y_pred, y_true, mult, out);
}